// round 5
// baseline (speedup 1.0000x reference)
#include <cuda_runtime.h>

// GCNStack: out = relu((A @ x) @ W1 + b1) @ W2 + b2
//   x:[B,N,64] f32, A COO (idx [2,E] int32 OR int64 -- detected at runtime), val f32
//   W1:[64,256], W2:[256,64]
// Pipeline per launch (all graph-capturable, no allocs):
//   0) detect idx dtype  1) zero counts  2) count rows  3) scan -> row_ptr/cursor
//   4) scatter -> CSR    5) gather -> y  6) persistent fused MLP (FFMA2)

#define B_CONST 4
#define CIN     64
#define HDIM    256
#define COUT    64
#define MAXN    65536
#define MAXE    2000000

typedef unsigned long long ull;

static __device__ int   g_is64;
static __device__ int   g_counts[MAXN];
static __device__ int   g_rowptr[MAXN + 1];
static __device__ int   g_cursor[MAXN];
static __device__ int   g_ecol[MAXE];
static __device__ float g_eval[MAXE];
static __device__ float g_y[(size_t)B_CONST * MAXN * CIN];   // [b][N][64]

// ---------------- f32x2 SIMD helpers (Blackwell packed fp32) ----------------
__device__ __forceinline__ ull ffma2(ull a, ull b, ull c) {
    ull d;
    asm("fma.rn.f32x2 %0, %1, %2, %3;" : "=l"(d) : "l"(a), "l"(b), "l"(c));
    return d;
}
__device__ __forceinline__ ull pk2(float x, float y) {
    ull r;
    asm("mov.b64 %0, {%1, %2};" : "=l"(r) : "f"(x), "f"(y));
    return r;
}
__device__ __forceinline__ float2 upk(ull v) {
    float2 r;
    asm("mov.b64 {%0, %1}, %2;" : "=f"(r.x), "=f"(r.y) : "l"(v));
    return r;
}

// ---------------- dtype probe ----------------
// If A_idx is int64 (indices < 2^31), every hi-word of the first 128 elements
// is 0. If it's int32, those slots are random indices in [0,N) -> nonzero with
// overwhelming probability. Deterministic given fixed input data.
__global__ void k_detect(const int* __restrict__ A32, int E) {
    if (threadIdx.x == 0) {
        int cnt = E < 128 ? E : 128;
        int is64 = 1;
        for (int i = 0; i < cnt; i++)
            if (A32[2 * i + 1] != 0) { is64 = 0; break; }
        g_is64 = is64;
    }
}

__device__ __forceinline__ int idx_row(const void* A, int e, int E, int is64, int N) {
    int r = is64 ? (int)((const long long*)A)[e] : ((const int*)A)[e];
    r = r < 0 ? 0 : (r >= N ? N - 1 : r);
    return r;
}
__device__ __forceinline__ int idx_col(const void* A, int e, int E, int is64, int N) {
    int c = is64 ? (int)((const long long*)A)[(size_t)E + e]
                 : ((const int*)A)[(size_t)E + e];
    c = c < 0 ? 0 : (c >= N ? N - 1 : c);
    return c;
}

// ---------------- CSR build ----------------
__global__ void k_zero(int n) {
    int i = blockIdx.x * blockDim.x + threadIdx.x;
    if (i < n) g_counts[i] = 0;
}

__global__ void k_count(const void* __restrict__ A, int E, int N) {
    int e = blockIdx.x * blockDim.x + threadIdx.x;
    if (e < E) atomicAdd(&g_counts[idx_row(A, e, E, g_is64, N)], 1);
}

// Single-CTA exclusive scan over counts[0..N) -> row_ptr, cursor
__global__ void k_scan(int N) {
    __shared__ int wsum[32];
    int t = threadIdx.x, lane = t & 31, w = t >> 5;
    int chunk = (N + 1023) >> 10;
    int s0 = t * chunk;
    int s1 = s0 + chunk; if (s1 > N) s1 = N;
    int s = 0;
    for (int i = s0; i < s1; i++) s += g_counts[i];
    int v = s;
#pragma unroll
    for (int o = 1; o < 32; o <<= 1) {
        int u = __shfl_up_sync(0xffffffffu, v, o);
        if (lane >= o) v += u;
    }
    if (lane == 31) wsum[w] = v;
    __syncthreads();
    if (w == 0) {
        int z = wsum[lane];
#pragma unroll
        for (int o = 1; o < 32; o <<= 1) {
            int u = __shfl_up_sync(0xffffffffu, z, o);
            if (lane >= o) z += u;
        }
        wsum[lane] = z;
    }
    __syncthreads();
    int run = (v - s) + (w ? wsum[w - 1] : 0);
    for (int i = s0; i < s1; i++) {
        g_rowptr[i] = run;
        g_cursor[i] = run;
        run += g_counts[i];
    }
    if (s1 == N && s0 <= N) g_rowptr[N] = run;
}

__global__ void k_scatter(const void* __restrict__ A,
                          const float* __restrict__ A_val, int E, int N) {
    int e = blockIdx.x * blockDim.x + threadIdx.x;
    if (e >= E) return;
    int is64 = g_is64;
    int r = idx_row(A, e, E, is64, N);
    int p = atomicAdd(&g_cursor[r], 1);
    g_ecol[p] = idx_col(A, e, E, is64, N);
    g_eval[p] = A_val[e];
}

// ---------------- gather: y[b][n][c] = sum_e val * x[b][col][c] ----------------
// One warp per node n, all 4 batches; lane covers channels {lane, lane+32}.
__global__ __launch_bounds__(256) void k_gather(const float* __restrict__ x, int N) {
    int wid = (blockIdx.x * blockDim.x + threadIdx.x) >> 5;
    int lane = threadIdx.x & 31;
    if (wid >= N) return;
    int beg = g_rowptr[wid], end = g_rowptr[wid + 1];
    float a0 = 0.f, a1 = 0.f, a2 = 0.f, a3 = 0.f, a4 = 0.f, a5 = 0.f, a6 = 0.f, a7 = 0.f;
    size_t bs = (size_t)N * CIN;
    const float* xl = x + lane;
    for (int i = beg; i < end; i++) {
        int c = g_ecol[i];
        float v = g_eval[i];
        const float* xp = xl + (size_t)c * CIN;
        a0 += v * xp[0];          a1 += v * xp[32];
        a2 += v * xp[bs];         a3 += v * xp[bs + 32];
        a4 += v * xp[2 * bs];     a5 += v * xp[2 * bs + 32];
        a6 += v * xp[3 * bs];     a7 += v * xp[3 * bs + 32];
    }
    float* yp = g_y + (size_t)wid * CIN + lane;
    yp[0] = a0;          yp[32] = a1;
    yp[bs] = a2;         yp[bs + 32] = a3;
    yp[2 * bs] = a4;     yp[2 * bs + 32] = a5;
    yp[3 * bs] = a6;     yp[3 * bs + 32] = a7;
}

// ---------------- fused MLP: out = relu(y@W1+b1)@W2+b2 ----------------
// Persistent: 1 CTA/SM, 256 threads, 64-node tiles.
// smem: W1(64K) W2(64K) b1 b2 Ytile(16K) Htile(64K) = ~209KB
__global__ __launch_bounds__(256, 1) void k_mlp(
    const float* __restrict__ W1, const float* __restrict__ b1,
    const float* __restrict__ W2, const float* __restrict__ b2,
    float* __restrict__ out, int N)
{
    extern __shared__ float sm[];
    float* sW1 = sm;                       // [64][256]
    float* sW2 = sW1 + CIN * HDIM;         // [256][64]
    float* sB1 = sW2 + HDIM * COUT;        // [256]
    float* sB2 = sB1 + HDIM;               // [64]
    float* sY  = sB2 + COUT;               // [64][64]
    float* sH  = sY + 64 * CIN;            // [64][256]

    int t = threadIdx.x;

    for (int i = t; i < CIN * HDIM / 4; i += 256)
        ((float4*)sW1)[i] = ((const float4*)W1)[i];
    for (int i = t; i < HDIM * COUT / 4; i += 256)
        ((float4*)sW2)[i] = ((const float4*)W2)[i];
    if (t < HDIM) sB1[t] = b1[t];
    if (t < COUT) sB2[t] = b2[t];

    int tn  = t >> 5;   // 0..7  : GEMM1 row group (8 rows)
    int tj  = t & 31;   // 0..31 : GEMM1 col quads {tj*4, 128+tj*4}
    int tn2 = t >> 4;   // 0..15 : GEMM2 row group (4 rows)
    int to2 = t & 15;   // 0..15 : GEMM2 col quad to2*4

    int nTiles = (N + 63) >> 6;
    int total = nTiles * B_CONST;

    for (int tile = blockIdx.x; tile < total; tile += gridDim.x) {
        int bI = tile / nTiles;
        int n0 = (tile - bI * nTiles) << 6;
        const float* yb = g_y + (size_t)bI * N * CIN;

        __syncthreads();   // previous tile fully consumed (sY & sH reads done)

        // ---- load y tile (zero-fill rows past N) ----
        int valid = N - n0; if (valid > 64) valid = 64;
        for (int i = t; i < 64 * (CIN / 4); i += 256) {
            int r = i >> 4, c4 = i & 15;
            float4 v = make_float4(0.f, 0.f, 0.f, 0.f);
            if (r < valid) v = *(const float4*)(yb + (size_t)(n0 + r) * CIN + c4 * 4);
            ((float4*)sY)[i] = v;
        }
        __syncthreads();

        // ---- GEMM1: h[64,256] = y[64,64] @ W1, 8x8 micro-tile, FFMA2 ----
        ull acc[8][4];
#pragma unroll
        for (int dn = 0; dn < 8; dn++)
#pragma unroll
            for (int q = 0; q < 4; q++) acc[dn][q] = 0ull;

#pragma unroll 4
        for (int k4 = 0; k4 < 16; k4++) {
            float4 a[8];
#pragma unroll
            for (int dn = 0; dn < 8; dn++)
                a[dn] = *(const float4*)&sY[(tn * 8 + dn) * CIN + k4 * 4];
#pragma unroll
            for (int kk = 0; kk < 4; kk++) {
                const float* wrow = &sW1[(k4 * 4 + kk) * HDIM];
                float4 w0 = *(const float4*)&wrow[tj * 4];
                float4 w1 = *(const float4*)&wrow[128 + tj * 4];
                ull w0lo = pk2(w0.x, w0.y), w0hi = pk2(w0.z, w0.w);
                ull w1lo = pk2(w1.x, w1.y), w1hi = pk2(w1.z, w1.w);
#pragma unroll
                for (int dn = 0; dn < 8; dn++) {
                    float av = ((const float*)&a[dn])[kk];
                    ull aa = pk2(av, av);
                    acc[dn][0] = ffma2(aa, w0lo, acc[dn][0]);
                    acc[dn][1] = ffma2(aa, w0hi, acc[dn][1]);
                    acc[dn][2] = ffma2(aa, w1lo, acc[dn][2]);
                    acc[dn][3] = ffma2(aa, w1hi, acc[dn][3]);
                }
            }
        }

        // ---- bias + relu -> sH ----
        {
            float4 bq0 = *(const float4*)&sB1[tj * 4];
            float4 bq1 = *(const float4*)&sB1[128 + tj * 4];
#pragma unroll
            for (int dn = 0; dn < 8; dn++) {
                float2 p0 = upk(acc[dn][0]), p1 = upk(acc[dn][1]);
                float4 h;
                h.x = fmaxf(p0.x + bq0.x, 0.f);
                h.y = fmaxf(p0.y + bq0.y, 0.f);
                h.z = fmaxf(p1.x + bq0.z, 0.f);
                h.w = fmaxf(p1.y + bq0.w, 0.f);
                *(float4*)&sH[(tn * 8 + dn) * HDIM + tj * 4] = h;
                p0 = upk(acc[dn][2]); p1 = upk(acc[dn][3]);
                h.x = fmaxf(p0.x + bq1.x, 0.f);
                h.y = fmaxf(p0.y + bq1.y, 0.f);
                h.z = fmaxf(p1.x + bq1.z, 0.f);
                h.w = fmaxf(p1.y + bq1.w, 0.f);
                *(float4*)&sH[(tn * 8 + dn) * HDIM + 128 + tj * 4] = h;
            }
        }
        __syncthreads();

        // ---- GEMM2: out[64,64] = h[64,256] @ W2, 4x4 micro-tile ----
        ull c2[4][2];
#pragma unroll
        for (int dn = 0; dn < 4; dn++) { c2[dn][0] = 0ull; c2[dn][1] = 0ull; }

#pragma unroll 4
        for (int k4 = 0; k4 < 64; k4++) {
            float4 a[4];
#pragma unroll
            for (int dn = 0; dn < 4; dn++)
                a[dn] = *(const float4*)&sH[(tn2 * 4 + dn) * HDIM + k4 * 4];
#pragma unroll
            for (int kk = 0; kk < 4; kk++) {
                float4 w = *(const float4*)&sW2[(k4 * 4 + kk) * COUT + to2 * 4];
                ull wlo = pk2(w.x, w.y), whi = pk2(w.z, w.w);
#pragma unroll
                for (int dn = 0; dn < 4; dn++) {
                    float av = ((const float*)&a[dn])[kk];
                    ull aa = pk2(av, av);
                    c2[dn][0] = ffma2(aa, wlo, c2[dn][0]);
                    c2[dn][1] = ffma2(aa, whi, c2[dn][1]);
                }
            }
        }

        // ---- bias + store ----
        {
            float4 b2q = *(const float4*)&sB2[to2 * 4];
#pragma unroll
            for (int dn = 0; dn < 4; dn++) {
                int n = n0 + tn2 * 4 + dn;
                if (n < N) {
                    float2 q0 = upk(c2[dn][0]), q1 = upk(c2[dn][1]);
                    float4 o4 = make_float4(q0.x + b2q.x, q0.y + b2q.y,
                                            q1.x + b2q.z, q1.y + b2q.w);
                    *(float4*)&out[((size_t)bI * N + n) * COUT + to2 * 4] = o4;
                }
            }
        }
    }
}

// ---------------- launch ----------------
extern "C" void kernel_launch(void* const* d_in, const int* in_sizes, int n_in,
                              void* d_out, int out_size) {
    const float* x  = (const float*)d_in[0];
    const void*  A  = d_in[1];
    const float* Av = (const float*)d_in[2];
    const float* W1 = (const float*)d_in[3];
    const float* b1 = (const float*)d_in[4];
    const float* W2 = (const float*)d_in[5];
    const float* b2 = (const float*)d_in[6];
    float* out = (float*)d_out;

    int E = in_sizes[1] / 2;
    int N = in_sizes[0] / (B_CONST * CIN);

    k_detect<<<1, 32>>>((const int*)A, E);
    k_zero<<<(N + 255) / 256, 256>>>(N);
    k_count<<<(E + 255) / 256, 256>>>(A, E, N);
    k_scan<<<1, 1024>>>(N);
    k_scatter<<<(E + 255) / 256, 256>>>(A, Av, E, N);
    k_gather<<<(N + 7) / 8, 256>>>(x, N);

    int smem = (CIN * HDIM + HDIM * COUT + HDIM + COUT + 64 * CIN + 64 * HDIM) * (int)sizeof(float);
    cudaFuncSetAttribute(k_mlp, cudaFuncAttributeMaxDynamicSharedMemorySize, smem);
    k_mlp<<<148, 256, smem>>>(W1, b1, W2, b2, out, N);
}

// round 6
// speedup vs baseline: 1.1713x; 1.1713x over previous
#include <cuda_runtime.h>

// GCNStack: out = relu((A @ x) @ W1 + b1) @ W2 + b2
//   x:[B,N,64] f32, A COO (idx [2,E] int32 OR int64 -- detected at runtime), val f32
//   W1:[64,256], W2:[256,64]
// Pipeline (graph-capturable, no allocs):
//   0) parallel dtype probe   1) zero counts   2) count rows
//   3) 3-phase parallel scan -> row_ptr/cursor 4) scatter -> CSR
//   5) gather (float2)        6) persistent fused MLP (FFMA2)

#define B_CONST 4
#define CIN     64
#define HDIM    256
#define COUT    64
#define MAXN    65536
#define MAXE    2000000
#define SCAN_CHUNK 2048          // elements per scan CTA
#define MAXBLK  (MAXN / SCAN_CHUNK)   // 32

typedef unsigned long long ull;

static __device__ int   g_is64;
static __device__ int   g_counts[MAXN];
static __device__ int   g_rowptr[MAXN + 1];
static __device__ int   g_cursor[MAXN];
static __device__ int   g_part[MAXBLK];
static __device__ int   g_partpre[MAXBLK];
static __device__ int   g_ecol[MAXE];
static __device__ float g_eval[MAXE];
static __device__ __align__(16) float g_y[(size_t)B_CONST * MAXN * CIN];  // [b][N][64]

// ---------------- f32x2 SIMD helpers (Blackwell packed fp32) ----------------
__device__ __forceinline__ ull ffma2(ull a, ull b, ull c) {
    ull d;
    asm("fma.rn.f32x2 %0, %1, %2, %3;" : "=l"(d) : "l"(a), "l"(b), "l"(c));
    return d;
}
__device__ __forceinline__ ull pk2(float x, float y) {
    ull r;
    asm("mov.b64 %0, {%1, %2};" : "=l"(r) : "f"(x), "f"(y));
    return r;
}
__device__ __forceinline__ float2 upk(ull v) {
    float2 r;
    asm("mov.b64 {%0, %1}, %2;" : "=f"(r.x), "=f"(r.y) : "l"(v));
    return r;
}

// ---------------- dtype probe (parallel) ----------------
// int64 indices < 2^31 -> all hi-words of first 128 elements are 0.
// int32 -> those slots hold random indices, nonzero w.p. ~1.
__global__ void k_detect(const int* __restrict__ A32, int E) {
    __shared__ int anybad;
    int t = threadIdx.x;
    if (t == 0) anybad = 0;
    __syncthreads();
    int cnt = E < 128 ? E : 128;
    if (t < cnt && A32[2 * t + 1] != 0) anybad = 1;
    __syncthreads();
    if (t == 0) g_is64 = !anybad;
}

__device__ __forceinline__ int idx_row(const void* A, int e, int E, int is64, int N) {
    int r = is64 ? (int)((const long long*)A)[e] : ((const int*)A)[e];
    r = r < 0 ? 0 : (r >= N ? N - 1 : r);
    return r;
}
__device__ __forceinline__ int idx_col(const void* A, int e, int E, int is64, int N) {
    int c = is64 ? (int)((const long long*)A)[(size_t)E + e]
                 : ((const int*)A)[(size_t)E + e];
    c = c < 0 ? 0 : (c >= N ? N - 1 : c);
    return c;
}

// ---------------- CSR build ----------------
__global__ void k_zero(int n) {
    int i = blockIdx.x * blockDim.x + threadIdx.x;
    if (i < n) g_counts[i] = 0;
}

__global__ void k_count(const void* __restrict__ A, int E, int N) {
    int e = blockIdx.x * blockDim.x + threadIdx.x;
    if (e < E) atomicAdd(&g_counts[idx_row(A, e, E, g_is64, N)], 1);
}

// ---- scan phase 1: per-CTA sum of SCAN_CHUNK counts ----
__global__ __launch_bounds__(256) void k_blocksum(int N) {
    __shared__ int wsum[8];
    int b = blockIdx.x, t = threadIdx.x;
    int base = b * SCAN_CHUNK + t * 8;
    int s = 0;
#pragma unroll
    for (int i = 0; i < 8; i++) {
        int id = base + i;
        s += (id < N) ? g_counts[id] : 0;
    }
#pragma unroll
    for (int o = 16; o > 0; o >>= 1) s += __shfl_down_sync(0xffffffffu, s, o);
    if ((t & 31) == 0) wsum[t >> 5] = s;
    __syncthreads();
    if (t == 0) {
        int tot = 0;
#pragma unroll
        for (int w = 0; w < 8; w++) tot += wsum[w];
        g_part[b] = tot;
    }
}

// ---- scan phase 2: 1 warp exclusive-scans the <=32 partials; rowptr[N]=E ----
__global__ void k_scanpart(int nblocks, int E, int N) {
    int lane = threadIdx.x;
    int v = (lane < nblocks) ? g_part[lane] : 0;
    int incl = v;
#pragma unroll
    for (int o = 1; o < 32; o <<= 1) {
        int u = __shfl_up_sync(0xffffffffu, incl, o);
        if (lane >= o) incl += u;
    }
    if (lane < nblocks) g_partpre[lane] = incl - v;
    if (lane == 0) g_rowptr[N] = E;
}

// ---- scan phase 3: per-CTA local exclusive scan + write rowptr/cursor ----
__global__ __launch_bounds__(256) void k_blockscan(int N) {
    __shared__ int wsum[8];
    int b = blockIdx.x, t = threadIdx.x;
    int lane = t & 31, w = t >> 5;
    int base = b * SCAN_CHUNK + t * 8;
    int v[8];
    int s = 0;
#pragma unroll
    for (int i = 0; i < 8; i++) {
        int id = base + i;
        v[i] = (id < N) ? g_counts[id] : 0;
        s += v[i];
    }
    int incl = s;
#pragma unroll
    for (int o = 1; o < 32; o <<= 1) {
        int u = __shfl_up_sync(0xffffffffu, incl, o);
        if (lane >= o) incl += u;
    }
    if (lane == 31) wsum[w] = incl;
    __syncthreads();
    if (w == 0 && lane < 8) {
        int z = wsum[lane];
#pragma unroll
        for (int o = 1; o < 8; o <<= 1) {
            int u = __shfl_up_sync(0xffu, z, o);
            if (lane >= o) z += u;
        }
        wsum[lane] = z;
    }
    __syncthreads();
    int run = g_partpre[b] + (incl - s) + (w ? wsum[w - 1] : 0);
#pragma unroll
    for (int i = 0; i < 8; i++) {
        int id = base + i;
        if (id < N) {
            g_rowptr[id] = run;
            g_cursor[id] = run;
            run += v[i];
        }
    }
}

__global__ void k_scatter(const void* __restrict__ A,
                          const float* __restrict__ A_val, int E, int N) {
    int e = blockIdx.x * blockDim.x + threadIdx.x;
    if (e >= E) return;
    int is64 = g_is64;
    int r = idx_row(A, e, E, is64, N);
    int p = atomicAdd(&g_cursor[r], 1);
    g_ecol[p] = idx_col(A, e, E, is64, N);
    g_eval[p] = A_val[e];
}

// ---------------- gather: y[b][n][c] = sum_e val * x[b][col][c] ----------------
// One warp per node n; lane covers channel pair {2*lane, 2*lane+1} (float2),
// all 4 batches per edge: 4 vector loads/lane/edge.
__global__ __launch_bounds__(256) void k_gather(const float* __restrict__ x, int N) {
    int wid = (blockIdx.x * blockDim.x + threadIdx.x) >> 5;
    int lane = threadIdx.x & 31;
    if (wid >= N) return;
    int beg = g_rowptr[wid], end = g_rowptr[wid + 1];
    float2 a0 = {0.f, 0.f}, a1 = {0.f, 0.f}, a2 = {0.f, 0.f}, a3 = {0.f, 0.f};
    size_t bs2 = (size_t)N * (CIN / 2);            // batch stride in float2
    const float2* xb = (const float2*)x + lane;
    for (int i = beg; i < end; i++) {
        int c = g_ecol[i];
        float v = g_eval[i];
        const float2* xp = xb + (size_t)c * (CIN / 2);
        float2 p;
        p = xp[0];        a0.x += v * p.x;  a0.y += v * p.y;
        p = xp[bs2];      a1.x += v * p.x;  a1.y += v * p.y;
        p = xp[2 * bs2];  a2.x += v * p.x;  a2.y += v * p.y;
        p = xp[3 * bs2];  a3.x += v * p.x;  a3.y += v * p.y;
    }
    float2* yp = (float2*)g_y + (size_t)wid * (CIN / 2) + lane;
    yp[0] = a0;  yp[bs2] = a1;  yp[2 * bs2] = a2;  yp[3 * bs2] = a3;
}

// ---------------- fused MLP: out = relu(y@W1+b1)@W2+b2 ----------------
// Persistent: 1 CTA/SM, 256 threads, 64-node tiles. ~209KB smem.
__global__ __launch_bounds__(256, 1) void k_mlp(
    const float* __restrict__ W1, const float* __restrict__ b1,
    const float* __restrict__ W2, const float* __restrict__ b2,
    float* __restrict__ out, int N)
{
    extern __shared__ float sm[];
    float* sW1 = sm;                       // [64][256]
    float* sW2 = sW1 + CIN * HDIM;         // [256][64]
    float* sB1 = sW2 + HDIM * COUT;        // [256]
    float* sB2 = sB1 + HDIM;               // [64]
    float* sY  = sB2 + COUT;               // [64][64]
    float* sH  = sY + 64 * CIN;            // [64][256]

    int t = threadIdx.x;

    for (int i = t; i < CIN * HDIM / 4; i += 256)
        ((float4*)sW1)[i] = ((const float4*)W1)[i];
    for (int i = t; i < HDIM * COUT / 4; i += 256)
        ((float4*)sW2)[i] = ((const float4*)W2)[i];
    if (t < HDIM) sB1[t] = b1[t];
    if (t < COUT) sB2[t] = b2[t];

    int tn  = t >> 5;   // 0..7  : GEMM1 row group (8 rows)
    int tj  = t & 31;   // 0..31 : GEMM1 col quads {tj*4, 128+tj*4}
    int tn2 = t >> 4;   // 0..15 : GEMM2 row group (4 rows)
    int to2 = t & 15;   // 0..15 : GEMM2 col quad to2*4

    int nTiles = (N + 63) >> 6;
    int total = nTiles * B_CONST;

    for (int tile = blockIdx.x; tile < total; tile += gridDim.x) {
        int bI = tile / nTiles;
        int n0 = (tile - bI * nTiles) << 6;
        const float* yb = g_y + (size_t)bI * N * CIN;

        __syncthreads();   // previous tile fully consumed

        int valid = N - n0; if (valid > 64) valid = 64;
        for (int i = t; i < 64 * (CIN / 4); i += 256) {
            int r = i >> 4, c4 = i & 15;
            float4 v = make_float4(0.f, 0.f, 0.f, 0.f);
            if (r < valid) v = *(const float4*)(yb + (size_t)(n0 + r) * CIN + c4 * 4);
            ((float4*)sY)[i] = v;
        }
        __syncthreads();

        // ---- GEMM1: h[64,256] = y[64,64] @ W1, 8x8 micro-tile, FFMA2 ----
        ull acc[8][4];
#pragma unroll
        for (int dn = 0; dn < 8; dn++)
#pragma unroll
            for (int q = 0; q < 4; q++) acc[dn][q] = 0ull;

#pragma unroll 4
        for (int k4 = 0; k4 < 16; k4++) {
            float4 a[8];
#pragma unroll
            for (int dn = 0; dn < 8; dn++)
                a[dn] = *(const float4*)&sY[(tn * 8 + dn) * CIN + k4 * 4];
#pragma unroll
            for (int kk = 0; kk < 4; kk++) {
                const float* wrow = &sW1[(k4 * 4 + kk) * HDIM];
                float4 w0 = *(const float4*)&wrow[tj * 4];
                float4 w1 = *(const float4*)&wrow[128 + tj * 4];
                ull w0lo = pk2(w0.x, w0.y), w0hi = pk2(w0.z, w0.w);
                ull w1lo = pk2(w1.x, w1.y), w1hi = pk2(w1.z, w1.w);
#pragma unroll
                for (int dn = 0; dn < 8; dn++) {
                    float av = ((const float*)&a[dn])[kk];
                    ull aa = pk2(av, av);
                    acc[dn][0] = ffma2(aa, w0lo, acc[dn][0]);
                    acc[dn][1] = ffma2(aa, w0hi, acc[dn][1]);
                    acc[dn][2] = ffma2(aa, w1lo, acc[dn][2]);
                    acc[dn][3] = ffma2(aa, w1hi, acc[dn][3]);
                }
            }
        }

        // ---- bias + relu -> sH ----
        {
            float4 bq0 = *(const float4*)&sB1[tj * 4];
            float4 bq1 = *(const float4*)&sB1[128 + tj * 4];
#pragma unroll
            for (int dn = 0; dn < 8; dn++) {
                float2 p0 = upk(acc[dn][0]), p1 = upk(acc[dn][1]);
                float4 h;
                h.x = fmaxf(p0.x + bq0.x, 0.f);
                h.y = fmaxf(p0.y + bq0.y, 0.f);
                h.z = fmaxf(p1.x + bq0.z, 0.f);
                h.w = fmaxf(p1.y + bq0.w, 0.f);
                *(float4*)&sH[(tn * 8 + dn) * HDIM + tj * 4] = h;
                p0 = upk(acc[dn][2]); p1 = upk(acc[dn][3]);
                h.x = fmaxf(p0.x + bq1.x, 0.f);
                h.y = fmaxf(p0.y + bq1.y, 0.f);
                h.z = fmaxf(p1.x + bq1.z, 0.f);
                h.w = fmaxf(p1.y + bq1.w, 0.f);
                *(float4*)&sH[(tn * 8 + dn) * HDIM + 128 + tj * 4] = h;
            }
        }
        __syncthreads();

        // ---- GEMM2: out[64,64] = h[64,256] @ W2, 4x4 micro-tile ----
        ull c2[4][2];
#pragma unroll
        for (int dn = 0; dn < 4; dn++) { c2[dn][0] = 0ull; c2[dn][1] = 0ull; }

#pragma unroll 4
        for (int k4 = 0; k4 < 64; k4++) {
            float4 a[4];
#pragma unroll
            for (int dn = 0; dn < 4; dn++)
                a[dn] = *(const float4*)&sH[(tn2 * 4 + dn) * HDIM + k4 * 4];
#pragma unroll
            for (int kk = 0; kk < 4; kk++) {
                float4 w = *(const float4*)&sW2[(k4 * 4 + kk) * COUT + to2 * 4];
                ull wlo = pk2(w.x, w.y), whi = pk2(w.z, w.w);
#pragma unroll
                for (int dn = 0; dn < 4; dn++) {
                    float av = ((const float*)&a[dn])[kk];
                    ull aa = pk2(av, av);
                    c2[dn][0] = ffma2(aa, wlo, c2[dn][0]);
                    c2[dn][1] = ffma2(aa, whi, c2[dn][1]);
                }
            }
        }

        // ---- bias + store ----
        {
            float4 b2q = *(const float4*)&sB2[to2 * 4];
#pragma unroll
            for (int dn = 0; dn < 4; dn++) {
                int n = n0 + tn2 * 4 + dn;
                if (n < N) {
                    float2 q0 = upk(c2[dn][0]), q1 = upk(c2[dn][1]);
                    float4 o4 = make_float4(q0.x + b2q.x, q0.y + b2q.y,
                                            q1.x + b2q.z, q1.y + b2q.w);
                    *(float4*)&out[((size_t)bI * N + n) * COUT + to2 * 4] = o4;
                }
            }
        }
    }
}

// ---------------- launch ----------------
extern "C" void kernel_launch(void* const* d_in, const int* in_sizes, int n_in,
                              void* d_out, int out_size) {
    const float* x  = (const float*)d_in[0];
    const void*  A  = d_in[1];
    const float* Av = (const float*)d_in[2];
    const float* W1 = (const float*)d_in[3];
    const float* b1 = (const float*)d_in[4];
    const float* W2 = (const float*)d_in[5];
    const float* b2 = (const float*)d_in[6];
    float* out = (float*)d_out;

    int E = in_sizes[1] / 2;
    int N = in_sizes[0] / (B_CONST * CIN);
    int nb = (N + SCAN_CHUNK - 1) / SCAN_CHUNK;

    k_detect<<<1, 128>>>((const int*)A, E);
    k_zero<<<(N + 255) / 256, 256>>>(N);
    k_count<<<(E + 255) / 256, 256>>>(A, E, N);
    k_blocksum<<<nb, 256>>>(N);
    k_scanpart<<<1, 32>>>(nb, E, N);
    k_blockscan<<<nb, 256>>>(N);
    k_scatter<<<(E + 255) / 256, 256>>>(A, Av, E, N);
    k_gather<<<(N + 7) / 8, 256>>>(x, N);

    int smem = (CIN * HDIM + HDIM * COUT + HDIM + COUT + 64 * CIN + 64 * HDIM) * (int)sizeof(float);
    cudaFuncSetAttribute(k_mlp, cudaFuncAttributeMaxDynamicSharedMemorySize, smem);
    k_mlp<<<148, 256, smem>>>(W1, b1, W2, b2, out, N);
}

// round 7
// speedup vs baseline: 1.2906x; 1.1019x over previous
#include <cuda_runtime.h>

// GCNStack: out = relu((A @ x) @ W1 + b1) @ W2 + b2
//   x:[B,N,64] f32, A COO (idx [2,E] int32 OR int64 -- detected at runtime), val f32
//   W1:[64,256], W2:[256,64]
// Pipeline (graph-capturable, no allocs):
//   1) zero counts + dtype probe   2) count rows
//   3) 3-phase parallel scan -> row_ptr/cursor   4) scatter -> CSR
//   5) gather (2 nodes/warp, float4)             6) persistent fused MLP (FFMA2, y-prefetch)

#define B_CONST 4
#define CIN     64
#define HDIM    256
#define COUT    64
#define MAXN    65536
#define MAXE    2000000
#define SCAN_CHUNK 2048
#define MAXBLK  (MAXN / SCAN_CHUNK)

typedef unsigned long long ull;

static __device__ int   g_is64;
static __device__ int   g_counts[MAXN];
static __device__ int   g_rowptr[MAXN + 1];
static __device__ int   g_cursor[MAXN];
static __device__ int   g_part[MAXBLK];
static __device__ int   g_partpre[MAXBLK];
static __device__ int   g_ecol[MAXE];
static __device__ float g_eval[MAXE];
static __device__ __align__(16) float g_y[(size_t)B_CONST * MAXN * CIN];  // [b][N][64]

// ---------------- f32x2 SIMD helpers (Blackwell packed fp32) ----------------
__device__ __forceinline__ ull ffma2(ull a, ull b, ull c) {
    ull d;
    asm("fma.rn.f32x2 %0, %1, %2, %3;" : "=l"(d) : "l"(a), "l"(b), "l"(c));
    return d;
}
__device__ __forceinline__ ull pk2(float x, float y) {
    ull r;
    asm("mov.b64 %0, {%1, %2};" : "=l"(r) : "f"(x), "f"(y));
    return r;
}
__device__ __forceinline__ float2 upk(ull v) {
    float2 r;
    asm("mov.b64 {%0, %1}, %2;" : "=f"(r.x), "=f"(r.y) : "l"(v));
    return r;
}

// ---------------- dtype helpers ----------------
__device__ __forceinline__ int idx_row(const void* A, int e, int E, int is64, int N) {
    int r = is64 ? (int)((const long long*)A)[e] : ((const int*)A)[e];
    r = r < 0 ? 0 : (r >= N ? N - 1 : r);
    return r;
}
__device__ __forceinline__ int idx_col(const void* A, int e, int E, int is64, int N) {
    int c = is64 ? (int)((const long long*)A)[(size_t)E + e]
                 : ((const int*)A)[(size_t)E + e];
    c = c < 0 ? 0 : (c >= N ? N - 1 : c);
    return c;
}

// ---------------- zero counts + fused dtype probe ----------------
// int64 indices < 2^31 -> hi-words of first 128 elements all 0.
// int32 -> those slots hold random indices, nonzero w.p. ~1.
__global__ void k_zero(const int* __restrict__ A32, int E, int n) {
    __shared__ int sbad;
    int t = threadIdx.x;
    int i = blockIdx.x * blockDim.x + t;
    if (i < n) g_counts[i] = 0;
    if (blockIdx.x == 0) {
        if (t == 0) sbad = 0;
        __syncthreads();
        int cnt = E < 128 ? E : 128;
        if (t < cnt && A32[2 * t + 1] != 0) sbad = 1;
        __syncthreads();
        if (t == 0) g_is64 = !sbad;
    }
}

__global__ void k_count(const void* __restrict__ A, int E, int N) {
    int e = blockIdx.x * blockDim.x + threadIdx.x;
    if (e < E) atomicAdd(&g_counts[idx_row(A, e, E, g_is64, N)], 1);
}

// ---- scan phase 1: per-CTA sum of SCAN_CHUNK counts ----
__global__ __launch_bounds__(256) void k_blocksum(int N) {
    __shared__ int wsum[8];
    int b = blockIdx.x, t = threadIdx.x;
    int base = b * SCAN_CHUNK + t * 8;
    int s = 0;
#pragma unroll
    for (int i = 0; i < 8; i++) {
        int id = base + i;
        s += (id < N) ? g_counts[id] : 0;
    }
#pragma unroll
    for (int o = 16; o > 0; o >>= 1) s += __shfl_down_sync(0xffffffffu, s, o);
    if ((t & 31) == 0) wsum[t >> 5] = s;
    __syncthreads();
    if (t == 0) {
        int tot = 0;
#pragma unroll
        for (int w = 0; w < 8; w++) tot += wsum[w];
        g_part[b] = tot;
    }
}

// ---- scan phase 2: 1 warp exclusive-scans the <=32 partials; rowptr[N]=E ----
__global__ void k_scanpart(int nblocks, int E, int N) {
    int lane = threadIdx.x;
    int v = (lane < nblocks) ? g_part[lane] : 0;
    int incl = v;
#pragma unroll
    for (int o = 1; o < 32; o <<= 1) {
        int u = __shfl_up_sync(0xffffffffu, incl, o);
        if (lane >= o) incl += u;
    }
    if (lane < nblocks) g_partpre[lane] = incl - v;
    if (lane == 0) g_rowptr[N] = E;
}

// ---- scan phase 3: per-CTA local exclusive scan + write rowptr/cursor ----
__global__ __launch_bounds__(256) void k_blockscan(int N) {
    __shared__ int wsum[8];
    int b = blockIdx.x, t = threadIdx.x;
    int lane = t & 31, w = t >> 5;
    int base = b * SCAN_CHUNK + t * 8;
    int v[8];
    int s = 0;
#pragma unroll
    for (int i = 0; i < 8; i++) {
        int id = base + i;
        v[i] = (id < N) ? g_counts[id] : 0;
        s += v[i];
    }
    int incl = s;
#pragma unroll
    for (int o = 1; o < 32; o <<= 1) {
        int u = __shfl_up_sync(0xffffffffu, incl, o);
        if (lane >= o) incl += u;
    }
    if (lane == 31) wsum[w] = incl;
    __syncthreads();
    if (w == 0 && lane < 8) {
        int z = wsum[lane];
#pragma unroll
        for (int o = 1; o < 8; o <<= 1) {
            int u = __shfl_up_sync(0xffu, z, o);
            if (lane >= o) z += u;
        }
        wsum[lane] = z;
    }
    __syncthreads();
    int run = g_partpre[b] + (incl - s) + (w ? wsum[w - 1] : 0);
#pragma unroll
    for (int i = 0; i < 8; i++) {
        int id = base + i;
        if (id < N) {
            g_rowptr[id] = run;
            g_cursor[id] = run;
            run += v[i];
        }
    }
}

__global__ void k_scatter(const void* __restrict__ A,
                          const float* __restrict__ A_val, int E, int N) {
    int e = blockIdx.x * blockDim.x + threadIdx.x;
    if (e >= E) return;
    int is64 = g_is64;
    int r = idx_row(A, e, E, is64, N);
    int p = atomicAdd(&g_cursor[r], 1);
    g_ecol[p] = idx_col(A, e, E, is64, N);
    g_eval[p] = A_val[e];
}

// ---------------- gather: y[b][n][c] = sum_e val * x[b][col][c] ----------------
// 2 nodes per warp: half-warp (16 lanes x float4 = 64 channels) per node, 4 batches.
// Per edge: 4 LDG.128 shared across the edge pair + merged metadata loads.
__global__ __launch_bounds__(256) void k_gather(const float* __restrict__ x, int N) {
    int gwarp = (blockIdx.x * blockDim.x + threadIdx.x) >> 5;
    int lane = threadIdx.x & 31;
    int half = lane >> 4;
    int lh   = lane & 15;
    int node = gwarp * 2 + half;
    bool vn = node < N;
    int beg = vn ? g_rowptr[node] : 0;
    int end = vn ? g_rowptr[node + 1] : 0;
    int deg = end - beg;
    int md = max(deg, __shfl_xor_sync(0xffffffffu, deg, 16));

    float4 a0 = {0.f,0.f,0.f,0.f}, a1 = a0, a2 = a0, a3 = a0;
    size_t bs4 = (size_t)N * 16;                 // batch stride in float4
    const float4* xb = (const float4*)x + lh;

    for (int j = 0; j < md; j++) {
        if (j < deg) {
            int c = g_ecol[beg + j];
            float v = g_eval[beg + j];
            const float4* xp = xb + (size_t)c * 16;
            float4 p;
            p = xp[0];
            a0.x += v*p.x; a0.y += v*p.y; a0.z += v*p.z; a0.w += v*p.w;
            p = xp[bs4];
            a1.x += v*p.x; a1.y += v*p.y; a1.z += v*p.z; a1.w += v*p.w;
            p = xp[2*bs4];
            a2.x += v*p.x; a2.y += v*p.y; a2.z += v*p.z; a2.w += v*p.w;
            p = xp[3*bs4];
            a3.x += v*p.x; a3.y += v*p.y; a3.z += v*p.z; a3.w += v*p.w;
        }
    }
    if (vn) {
        float4* yp = (float4*)g_y + (size_t)node * 16 + lh;
        yp[0] = a0;  yp[bs4] = a1;  yp[2*bs4] = a2;  yp[3*bs4] = a3;
    }
}

// ---------------- fused MLP: out = relu(y@W1+b1)@W2+b2 ----------------
// Persistent: 1 CTA/SM, 256 threads, 64-node tiles. ~209KB smem.
// Next tile's y is prefetched into registers during GEMM2.
__global__ __launch_bounds__(256, 1) void k_mlp(
    const float* __restrict__ W1, const float* __restrict__ b1,
    const float* __restrict__ W2, const float* __restrict__ b2,
    float* __restrict__ out, int N)
{
    extern __shared__ float sm[];
    float* sW1 = sm;                       // [64][256]
    float* sW2 = sW1 + CIN * HDIM;         // [256][64]
    float* sB1 = sW2 + HDIM * COUT;        // [256]
    float* sB2 = sB1 + HDIM;               // [64]
    float* sY  = sB2 + COUT;               // [64][64]
    float* sH  = sY + 64 * CIN;            // [64][256]

    int t = threadIdx.x;

    for (int i = t; i < CIN * HDIM / 4; i += 256)
        ((float4*)sW1)[i] = ((const float4*)W1)[i];
    for (int i = t; i < HDIM * COUT / 4; i += 256)
        ((float4*)sW2)[i] = ((const float4*)W2)[i];
    if (t < HDIM) sB1[t] = b1[t];
    if (t < COUT) sB2[t] = b2[t];

    int tn  = t >> 5;   // GEMM1 row group (8 rows)
    int tj  = t & 31;   // GEMM1 col quads {tj*4, 128+tj*4}
    int tn2 = t >> 4;   // GEMM2 row group (4 rows)
    int to2 = t & 15;   // GEMM2 col quad

    int nTiles = (N + 63) >> 6;
    int total = nTiles * B_CONST;

    // prefetch helper: load this thread's 4 float4 slots of tile's y into regs
    auto prefetch = [&](int tile, float4* pre) {
        int bI = tile / nTiles;
        int n0 = (tile - bI * nTiles) << 6;
        const float* yb = g_y + (size_t)bI * N * CIN;
        int valid = N - n0; if (valid > 64) valid = 64;
#pragma unroll
        for (int q = 0; q < 4; q++) {
            int i = t + q * 256;             // index in [0,1024): r=i>>4, c4=i&15
            int r = i >> 4, c4 = i & 15;
            float4 v = make_float4(0.f, 0.f, 0.f, 0.f);
            if (r < valid) v = *(const float4*)(yb + (size_t)(n0 + r) * CIN + c4 * 4);
            pre[q] = v;
        }
    };

    float4 pre[4];
    if (blockIdx.x < total) prefetch(blockIdx.x, pre);

    for (int tile = blockIdx.x; tile < total; tile += gridDim.x) {
        int bI = tile / nTiles;
        int n0 = (tile - bI * nTiles) << 6;

        __syncthreads();   // previous tile fully consumed

        // ---- store prefetched y tile to smem ----
#pragma unroll
        for (int q = 0; q < 4; q++)
            ((float4*)sY)[t + q * 256] = pre[q];
        __syncthreads();

        // ---- GEMM1: h[64,256] = y[64,64] @ W1, 8x8 micro-tile, FFMA2 ----
        ull acc[8][4];
#pragma unroll
        for (int dn = 0; dn < 8; dn++)
#pragma unroll
            for (int q = 0; q < 4; q++) acc[dn][q] = 0ull;

#pragma unroll 4
        for (int k4 = 0; k4 < 16; k4++) {
            float4 a[8];
#pragma unroll
            for (int dn = 0; dn < 8; dn++)
                a[dn] = *(const float4*)&sY[(tn * 8 + dn) * CIN + k4 * 4];
#pragma unroll
            for (int kk = 0; kk < 4; kk++) {
                const float* wrow = &sW1[(k4 * 4 + kk) * HDIM];
                float4 w0 = *(const float4*)&wrow[tj * 4];
                float4 w1 = *(const float4*)&wrow[128 + tj * 4];
                ull w0lo = pk2(w0.x, w0.y), w0hi = pk2(w0.z, w0.w);
                ull w1lo = pk2(w1.x, w1.y), w1hi = pk2(w1.z, w1.w);
#pragma unroll
                for (int dn = 0; dn < 8; dn++) {
                    float av = ((const float*)&a[dn])[kk];
                    ull aa = pk2(av, av);
                    acc[dn][0] = ffma2(aa, w0lo, acc[dn][0]);
                    acc[dn][1] = ffma2(aa, w0hi, acc[dn][1]);
                    acc[dn][2] = ffma2(aa, w1lo, acc[dn][2]);
                    acc[dn][3] = ffma2(aa, w1hi, acc[dn][3]);
                }
            }
        }

        // ---- bias + relu -> sH ----
        {
            float4 bq0 = *(const float4*)&sB1[tj * 4];
            float4 bq1 = *(const float4*)&sB1[128 + tj * 4];
#pragma unroll
            for (int dn = 0; dn < 8; dn++) {
                float2 p0 = upk(acc[dn][0]), p1 = upk(acc[dn][1]);
                float4 h;
                h.x = fmaxf(p0.x + bq0.x, 0.f);
                h.y = fmaxf(p0.y + bq0.y, 0.f);
                h.z = fmaxf(p1.x + bq0.z, 0.f);
                h.w = fmaxf(p1.y + bq0.w, 0.f);
                *(float4*)&sH[(tn * 8 + dn) * HDIM + tj * 4] = h;
                p0 = upk(acc[dn][2]); p1 = upk(acc[dn][3]);
                h.x = fmaxf(p0.x + bq1.x, 0.f);
                h.y = fmaxf(p0.y + bq1.y, 0.f);
                h.z = fmaxf(p1.x + bq1.z, 0.f);
                h.w = fmaxf(p1.y + bq1.w, 0.f);
                *(float4*)&sH[(tn * 8 + dn) * HDIM + 128 + tj * 4] = h;
            }
        }
        __syncthreads();

        // ---- prefetch next tile's y while GEMM2 runs (sY is dead here) ----
        int next = tile + gridDim.x;
        if (next < total) prefetch(next, pre);

        // ---- GEMM2: out[64,64] = h[64,256] @ W2, 4x4 micro-tile ----
        ull c2[4][2];
#pragma unroll
        for (int dn = 0; dn < 4; dn++) { c2[dn][0] = 0ull; c2[dn][1] = 0ull; }

#pragma unroll 4
        for (int k4 = 0; k4 < 64; k4++) {
            float4 a[4];
#pragma unroll
            for (int dn = 0; dn < 4; dn++)
                a[dn] = *(const float4*)&sH[(tn2 * 4 + dn) * HDIM + k4 * 4];
#pragma unroll
            for (int kk = 0; kk < 4; kk++) {
                float4 w = *(const float4*)&sW2[(k4 * 4 + kk) * COUT + to2 * 4];
                ull wlo = pk2(w.x, w.y), whi = pk2(w.z, w.w);
#pragma unroll
                for (int dn = 0; dn < 4; dn++) {
                    float av = ((const float*)&a[dn])[kk];
                    ull aa = pk2(av, av);
                    c2[dn][0] = ffma2(aa, wlo, c2[dn][0]);
                    c2[dn][1] = ffma2(aa, whi, c2[dn][1]);
                }
            }
        }

        // ---- bias + store ----
        {
            float4 b2q = *(const float4*)&sB2[to2 * 4];
#pragma unroll
            for (int dn = 0; dn < 4; dn++) {
                int n = n0 + tn2 * 4 + dn;
                if (n < N) {
                    float2 q0 = upk(c2[dn][0]), q1 = upk(c2[dn][1]);
                    float4 o4 = make_float4(q0.x + b2q.x, q0.y + b2q.y,
                                            q1.x + b2q.z, q1.y + b2q.w);
                    *(float4*)&out[((size_t)bI * N + n) * COUT + to2 * 4] = o4;
                }
            }
        }
    }
}

// ---------------- launch ----------------
extern "C" void kernel_launch(void* const* d_in, const int* in_sizes, int n_in,
                              void* d_out, int out_size) {
    const float* x  = (const float*)d_in[0];
    const void*  A  = d_in[1];
    const float* Av = (const float*)d_in[2];
    const float* W1 = (const float*)d_in[3];
    const float* b1 = (const float*)d_in[4];
    const float* W2 = (const float*)d_in[5];
    const float* b2 = (const float*)d_in[6];
    float* out = (float*)d_out;

    int E = in_sizes[1] / 2;
    int N = in_sizes[0] / (B_CONST * CIN);
    int nb = (N + SCAN_CHUNK - 1) / SCAN_CHUNK;

    k_zero<<<(N + 255) / 256, 256>>>((const int*)A, E, N);
    k_count<<<(E + 255) / 256, 256>>>(A, E, N);
    k_blocksum<<<nb, 256>>>(N);
    k_scanpart<<<1, 32>>>(nb, E, N);
    k_blockscan<<<nb, 256>>>(N);
    k_scatter<<<(E + 255) / 256, 256>>>(A, Av, E, N);
    k_gather<<<(N + 15) / 16, 256>>>(x, N);

    int smem = (CIN * HDIM + HDIM * COUT + HDIM + COUT + 64 * CIN + 64 * HDIM) * (int)sizeof(float);
    cudaFuncSetAttribute(k_mlp, cudaFuncAttributeMaxDynamicSharedMemorySize, smem);
    k_mlp<<<148, 256, smem>>>(W1, b1, W2, b2, out, N);
}

// round 8
// speedup vs baseline: 1.3091x; 1.0143x over previous
#include <cuda_runtime.h>

// GCNStack: out = relu((A @ x) @ W1 + b1) @ W2 + b2
//   x:[B,N,64] f32, A COO (idx [2,E] int32/int64 autodetected), val f32
//   W1:[64,256], W2:[256,64]
// Pipeline (graph-capturable, no allocs):
//   1) zero counts + dtype probe   2) count rows
//   3) 3-phase parallel scan -> row_ptr/cursor   4) scatter -> CSR
//   5) persistent fused GATHER+MLP: 8 compute warps (FFMA2 GEMMs) +
//      8 gather warps building next tile's y into double-buffered smem.

#define B_CONST 4
#define CIN     64
#define HDIM    256
#define COUT    64
#define MAXN    65536
#define MAXE    2000000
#define SCAN_CHUNK 2048
#define MAXBLK  (MAXN / SCAN_CHUNK)

typedef unsigned long long ull;

static __device__ int   g_is64;
static __device__ int   g_counts[MAXN];
static __device__ int   g_rowptr[MAXN + 1];
static __device__ int   g_cursor[MAXN];
static __device__ int   g_part[MAXBLK];
static __device__ int   g_partpre[MAXBLK];
static __device__ int   g_ecol[MAXE];
static __device__ float g_eval[MAXE];

// ---------------- f32x2 SIMD helpers ----------------
__device__ __forceinline__ ull ffma2(ull a, ull b, ull c) {
    ull d;
    asm("fma.rn.f32x2 %0, %1, %2, %3;" : "=l"(d) : "l"(a), "l"(b), "l"(c));
    return d;
}
__device__ __forceinline__ ull pk2(float x, float y) {
    ull r;
    asm("mov.b64 %0, {%1, %2};" : "=l"(r) : "f"(x), "f"(y));
    return r;
}
__device__ __forceinline__ float2 upk(ull v) {
    float2 r;
    asm("mov.b64 {%0, %1}, %2;" : "=f"(r.x), "=f"(r.y) : "l"(v));
    return r;
}

// ---------------- dtype helpers ----------------
__device__ __forceinline__ int idx_row(const void* A, int e, int E, int is64, int N) {
    int r = is64 ? (int)((const long long*)A)[e] : ((const int*)A)[e];
    r = r < 0 ? 0 : (r >= N ? N - 1 : r);
    return r;
}
__device__ __forceinline__ int idx_col(const void* A, int e, int E, int is64, int N) {
    int c = is64 ? (int)((const long long*)A)[(size_t)E + e]
                 : ((const int*)A)[(size_t)E + e];
    c = c < 0 ? 0 : (c >= N ? N - 1 : c);
    return c;
}

// ---------------- zero counts + fused dtype probe ----------------
__global__ void k_zero(const int* __restrict__ A32, int E, int n) {
    __shared__ int sbad;
    int t = threadIdx.x;
    int i = blockIdx.x * blockDim.x + t;
    if (i < n) g_counts[i] = 0;
    if (blockIdx.x == 0) {
        if (t == 0) sbad = 0;
        __syncthreads();
        int cnt = E < 128 ? E : 128;
        if (t < cnt && A32[2 * t + 1] != 0) sbad = 1;
        __syncthreads();
        if (t == 0) g_is64 = !sbad;
    }
}

__global__ void k_count(const void* __restrict__ A, int E, int N) {
    int e = blockIdx.x * blockDim.x + threadIdx.x;
    if (e < E) atomicAdd(&g_counts[idx_row(A, e, E, g_is64, N)], 1);
}

// ---- scan phase 1 ----
__global__ __launch_bounds__(256) void k_blocksum(int N) {
    __shared__ int wsum[8];
    int b = blockIdx.x, t = threadIdx.x;
    int base = b * SCAN_CHUNK + t * 8;
    int s = 0;
#pragma unroll
    for (int i = 0; i < 8; i++) {
        int id = base + i;
        s += (id < N) ? g_counts[id] : 0;
    }
#pragma unroll
    for (int o = 16; o > 0; o >>= 1) s += __shfl_down_sync(0xffffffffu, s, o);
    if ((t & 31) == 0) wsum[t >> 5] = s;
    __syncthreads();
    if (t == 0) {
        int tot = 0;
#pragma unroll
        for (int w = 0; w < 8; w++) tot += wsum[w];
        g_part[b] = tot;
    }
}

// ---- scan phase 2 ----
__global__ void k_scanpart(int nblocks, int E, int N) {
    int lane = threadIdx.x;
    int v = (lane < nblocks) ? g_part[lane] : 0;
    int incl = v;
#pragma unroll
    for (int o = 1; o < 32; o <<= 1) {
        int u = __shfl_up_sync(0xffffffffu, incl, o);
        if (lane >= o) incl += u;
    }
    if (lane < nblocks) g_partpre[lane] = incl - v;
    if (lane == 0) g_rowptr[N] = E;
}

// ---- scan phase 3 ----
__global__ __launch_bounds__(256) void k_blockscan(int N) {
    __shared__ int wsum[8];
    int b = blockIdx.x, t = threadIdx.x;
    int lane = t & 31, w = t >> 5;
    int base = b * SCAN_CHUNK + t * 8;
    int v[8];
    int s = 0;
#pragma unroll
    for (int i = 0; i < 8; i++) {
        int id = base + i;
        v[i] = (id < N) ? g_counts[id] : 0;
        s += v[i];
    }
    int incl = s;
#pragma unroll
    for (int o = 1; o < 32; o <<= 1) {
        int u = __shfl_up_sync(0xffffffffu, incl, o);
        if (lane >= o) incl += u;
    }
    if (lane == 31) wsum[w] = incl;
    __syncthreads();
    if (w == 0 && lane < 8) {
        int z = wsum[lane];
#pragma unroll
        for (int o = 1; o < 8; o <<= 1) {
            int u = __shfl_up_sync(0xffu, z, o);
            if (lane >= o) z += u;
        }
        wsum[lane] = z;
    }
    __syncthreads();
    int run = g_partpre[b] + (incl - s) + (w ? wsum[w - 1] : 0);
#pragma unroll
    for (int i = 0; i < 8; i++) {
        int id = base + i;
        if (id < N) {
            g_rowptr[id] = run;
            g_cursor[id] = run;
            run += v[i];
        }
    }
}

__global__ void k_scatter(const void* __restrict__ A,
                          const float* __restrict__ A_val, int E, int N) {
    int e = blockIdx.x * blockDim.x + threadIdx.x;
    if (e >= E) return;
    int is64 = g_is64;
    int r = idx_row(A, e, E, is64, N);
    int p = atomicAdd(&g_cursor[r], 1);
    g_ecol[p] = idx_col(A, e, E, is64, N);
    g_eval[p] = A_val[e];
}

// ---------------- fused gather + MLP ----------------
// 512 threads: warps 0-7 compute (256 thr), warps 8-15 gather (256 thr).
// smem: W1 64K | W2 64K | b1 1K | b2 .25K | sY0 16K | sY1 16K | sH 64K = 225.25KB
// Per tile: compute runs GEMM1 -> relu -> GEMM2 on sY[buf] while gather
// warps build sY[buf^1] for tile+gridDim. One __syncthreads per tile.
__global__ __launch_bounds__(512, 1) void k_fused(
    const float* __restrict__ x,
    const float* __restrict__ W1, const float* __restrict__ b1,
    const float* __restrict__ W2, const float* __restrict__ b2,
    float* __restrict__ out, int N)
{
    extern __shared__ float sm[];
    float* sW1 = sm;                        // [64][256]
    float* sW2 = sW1 + CIN * HDIM;          // [256][64]
    float* sB1 = sW2 + HDIM * COUT;         // [256]
    float* sB2 = sB1 + HDIM;                // [64]
    float* sY0 = sB2 + COUT;                // [64][64]
    float* sY1 = sY0 + 64 * CIN;            // [64][64]
    float* sH  = sY1 + 64 * CIN;            // [64][256]

    int t = threadIdx.x;
    int wid = t >> 5;
    bool isCompute = (wid < 8);

    int nTiles = (N + 63) >> 6;
    int total = nTiles * B_CONST;

    // -------- gather helper: build tile's y into buf --------
    // 16 half-warps x 4 nodes; lane lh covers channels [lh*4, lh*4+4).
    auto gather_tile = [&](int tile, float* buf) {
        int gt = t - 256;          // 0..255
        int hw = gt >> 4;          // 0..15
        int lh = gt & 15;          // 0..15
        int bI = tile / nTiles;
        int n0 = (tile - bI * nTiles) << 6;
        const float4* xb = (const float4*)x + (size_t)bI * N * 16 + lh;
#pragma unroll
        for (int j = 0; j < 4; j++) {
            int nl = hw * 4 + j;          // local row 0..63
            int node = n0 + nl;
            float4 acc = make_float4(0.f, 0.f, 0.f, 0.f);
            if (node < N) {
                int beg = g_rowptr[node], end = g_rowptr[node + 1];
                int i = beg;
                for (; i + 4 <= end; i += 4) {
                    int   c0 = g_ecol[i],     c1 = g_ecol[i + 1];
                    int   c2 = g_ecol[i + 2], c3 = g_ecol[i + 3];
                    float v0 = g_eval[i],     v1 = g_eval[i + 1];
                    float v2 = g_eval[i + 2], v3 = g_eval[i + 3];
                    float4 p0 = xb[(size_t)c0 * 16];
                    float4 p1 = xb[(size_t)c1 * 16];
                    float4 p2 = xb[(size_t)c2 * 16];
                    float4 p3 = xb[(size_t)c3 * 16];
                    acc.x += v0 * p0.x; acc.y += v0 * p0.y; acc.z += v0 * p0.z; acc.w += v0 * p0.w;
                    acc.x += v1 * p1.x; acc.y += v1 * p1.y; acc.z += v1 * p1.z; acc.w += v1 * p1.w;
                    acc.x += v2 * p2.x; acc.y += v2 * p2.y; acc.z += v2 * p2.z; acc.w += v2 * p2.w;
                    acc.x += v3 * p3.x; acc.y += v3 * p3.y; acc.z += v3 * p3.z; acc.w += v3 * p3.w;
                }
                for (; i < end; i++) {
                    int c = g_ecol[i];
                    float v = g_eval[i];
                    float4 p = xb[(size_t)c * 16];
                    acc.x += v * p.x; acc.y += v * p.y; acc.z += v * p.z; acc.w += v * p.w;
                }
            }
            ((float4*)buf)[nl * 16 + lh] = acc;
        }
    };

    // -------- prologue: compute warps load weights, gather warps build tile0 --------
    if (isCompute) {
        for (int i = t; i < CIN * HDIM / 4; i += 256)
            ((float4*)sW1)[i] = ((const float4*)W1)[i];
        for (int i = t; i < HDIM * COUT / 4; i += 256)
            ((float4*)sW2)[i] = ((const float4*)W2)[i];
        if (t < HDIM) sB1[t] = b1[t];
        if (t < COUT) sB2[t] = b2[t];
    } else {
        if ((int)blockIdx.x < total) gather_tile(blockIdx.x, sY0);
    }
    __syncthreads();

    int tn  = t >> 5;   // compute: GEMM1 row group
    int tj  = t & 31;   // GEMM1 col quads {tj*4, 128+tj*4}
    int tn2 = t >> 4;   // GEMM2 row group (4 rows)
    int to2 = t & 15;   // GEMM2 col quad

    int buf = 0;
    for (int tile = blockIdx.x; tile < total; tile += gridDim.x, buf ^= 1) {
        float* sY = buf ? sY1 : sY0;

        if (isCompute) {
            int bI = tile / nTiles;
            int n0 = (tile - bI * nTiles) << 6;

            // ---- GEMM1: h[64,256] = y[64,64] @ W1, 8x8 micro-tile, FFMA2 ----
            ull acc[8][4];
#pragma unroll
            for (int dn = 0; dn < 8; dn++)
#pragma unroll
                for (int q = 0; q < 4; q++) acc[dn][q] = 0ull;

#pragma unroll 4
            for (int k4 = 0; k4 < 16; k4++) {
                float4 a[8];
#pragma unroll
                for (int dn = 0; dn < 8; dn++)
                    a[dn] = *(const float4*)&sY[(tn * 8 + dn) * CIN + k4 * 4];
#pragma unroll
                for (int kk = 0; kk < 4; kk++) {
                    const float* wrow = &sW1[(k4 * 4 + kk) * HDIM];
                    float4 w0 = *(const float4*)&wrow[tj * 4];
                    float4 w1 = *(const float4*)&wrow[128 + tj * 4];
                    ull w0lo = pk2(w0.x, w0.y), w0hi = pk2(w0.z, w0.w);
                    ull w1lo = pk2(w1.x, w1.y), w1hi = pk2(w1.z, w1.w);
#pragma unroll
                    for (int dn = 0; dn < 8; dn++) {
                        float av = ((const float*)&a[dn])[kk];
                        ull aa = pk2(av, av);
                        acc[dn][0] = ffma2(aa, w0lo, acc[dn][0]);
                        acc[dn][1] = ffma2(aa, w0hi, acc[dn][1]);
                        acc[dn][2] = ffma2(aa, w1lo, acc[dn][2]);
                        acc[dn][3] = ffma2(aa, w1hi, acc[dn][3]);
                    }
                }
            }

            // ---- bias + relu -> sH ----
            {
                float4 bq0 = *(const float4*)&sB1[tj * 4];
                float4 bq1 = *(const float4*)&sB1[128 + tj * 4];
#pragma unroll
                for (int dn = 0; dn < 8; dn++) {
                    float2 p0 = upk(acc[dn][0]), p1 = upk(acc[dn][1]);
                    float4 h;
                    h.x = fmaxf(p0.x + bq0.x, 0.f);
                    h.y = fmaxf(p0.y + bq0.y, 0.f);
                    h.z = fmaxf(p1.x + bq0.z, 0.f);
                    h.w = fmaxf(p1.y + bq0.w, 0.f);
                    *(float4*)&sH[(tn * 8 + dn) * HDIM + tj * 4] = h;
                    p0 = upk(acc[dn][2]); p1 = upk(acc[dn][3]);
                    h.x = fmaxf(p0.x + bq1.x, 0.f);
                    h.y = fmaxf(p0.y + bq1.y, 0.f);
                    h.z = fmaxf(p1.x + bq1.z, 0.f);
                    h.w = fmaxf(p1.y + bq1.w, 0.f);
                    *(float4*)&sH[(tn * 8 + dn) * HDIM + 128 + tj * 4] = h;
                }
            }
            // compute-warp-only barrier (sH write -> read)
            asm volatile("bar.sync 1, 256;" ::: "memory");

            // ---- GEMM2: out[64,64] = h[64,256] @ W2, 4x4 micro-tile ----
            ull c2[4][2];
#pragma unroll
            for (int dn = 0; dn < 4; dn++) { c2[dn][0] = 0ull; c2[dn][1] = 0ull; }

#pragma unroll 4
            for (int k4 = 0; k4 < 64; k4++) {
                float4 a[4];
#pragma unroll
                for (int dn = 0; dn < 4; dn++)
                    a[dn] = *(const float4*)&sH[(tn2 * 4 + dn) * HDIM + k4 * 4];
#pragma unroll
                for (int kk = 0; kk < 4; kk++) {
                    float4 w = *(const float4*)&sW2[(k4 * 4 + kk) * COUT + to2 * 4];
                    ull wlo = pk2(w.x, w.y), whi = pk2(w.z, w.w);
#pragma unroll
                    for (int dn = 0; dn < 4; dn++) {
                        float av = ((const float*)&a[dn])[kk];
                        ull aa = pk2(av, av);
                        c2[dn][0] = ffma2(aa, wlo, c2[dn][0]);
                        c2[dn][1] = ffma2(aa, whi, c2[dn][1]);
                    }
                }
            }

            // ---- bias + store ----
            {
                float4 b2q = *(const float4*)&sB2[to2 * 4];
#pragma unroll
                for (int dn = 0; dn < 4; dn++) {
                    int n = n0 + tn2 * 4 + dn;
                    if (n < N) {
                        float2 q0 = upk(c2[dn][0]), q1 = upk(c2[dn][1]);
                        float4 o4 = make_float4(q0.x + b2q.x, q0.y + b2q.y,
                                                q1.x + b2q.z, q1.y + b2q.w);
                        *(float4*)&out[((size_t)bI * N + n) * COUT + to2 * 4] = o4;
                    }
                }
            }
        } else {
            // ---- gather warps: build next tile's y while compute runs ----
            int next = tile + gridDim.x;
            if (next < total) gather_tile(next, buf ? sY0 : sY1);
        }

        __syncthreads();   // sY[buf] consumed; sY[buf^1] ready
    }
}

// ---------------- launch ----------------
extern "C" void kernel_launch(void* const* d_in, const int* in_sizes, int n_in,
                              void* d_out, int out_size) {
    const float* x  = (const float*)d_in[0];
    const void*  A  = d_in[1];
    const float* Av = (const float*)d_in[2];
    const float* W1 = (const float*)d_in[3];
    const float* b1 = (const float*)d_in[4];
    const float* W2 = (const float*)d_in[5];
    const float* b2 = (const float*)d_in[6];
    float* out = (float*)d_out;

    int E = in_sizes[1] / 2;
    int N = in_sizes[0] / (B_CONST * CIN);
    int nb = (N + SCAN_CHUNK - 1) / SCAN_CHUNK;

    k_zero<<<(N + 255) / 256, 256>>>((const int*)A, E, N);
    k_count<<<(E + 255) / 256, 256>>>(A, E, N);
    k_blocksum<<<nb, 256>>>(N);
    k_scanpart<<<1, 32>>>(nb, E, N);
    k_blockscan<<<nb, 256>>>(N);
    k_scatter<<<(E + 255) / 256, 256>>>(A, Av, E, N);

    int smem = (CIN * HDIM + HDIM * COUT + HDIM + COUT + 2 * 64 * CIN + 64 * HDIM)
               * (int)sizeof(float);
    cudaFuncSetAttribute(k_fused, cudaFuncAttributeMaxDynamicSharedMemorySize, smem);
    k_fused<<<148, 512, smem>>>(x, W1, b1, W2, b2, out, N);
}